// round 2
// baseline (speedup 1.0000x reference)
#include <cuda_runtime.h>

// ============================================================================
// DifferentialAttention — round 2 (round-1 design, re-bench after infra fail;
// split-K slabs trimmed 32->8 to shrink static scratch 122MB -> 98MB)
//
// Algebraic rewrite:
//   out = diff @ x @ (Wv@Wo) + (1-lam)*(bv@Wo) + bo
// where diff = softmax(Q1K1^T*s) - lam*softmax(Q2K2^T*s),
// reducing 220 GF -> ~28 GF and removing the [4096 x 8192] intermediates.
//
// Shapes: B=2, S=2048, D=512. All GEMM dims divisible by 128 (M,N) / 16 (K),
// so the tiled SGEMM below runs bounds-check-free.
// ============================================================================

#define BATCH 2
#define SEQ   2048
#define DMODEL 512
#define W2_SPLITS 8

// ---------------------------------------------------------------------------
// Scratch (device globals — no allocation allowed in kernel_launch)
// ---------------------------------------------------------------------------
__device__ float g_qkv[4096 * 1024];              // [B*S, 1024]  Q1|Q2|K1|K2
__device__ float g_P1 [2 * 2048 * 2048];          // logits/probs map 1
__device__ float g_P2 [2 * 2048 * 2048];          // logits/probs map 2
__device__ float g_t  [4096 * 512];               // diff @ x
__device__ float g_W2p[W2_SPLITS * 512 * 512];    // split-K partials of Wv@Wo
__device__ float g_W2 [512 * 512];                // Wv @ Wo
__device__ float g_bfp[64 * 512];                 // partials of bv @ Wo
__device__ float g_bfin[512];                     // (1-lam)*(bv@Wo) + bo
__device__ float g_lam;

// ---------------------------------------------------------------------------
// Fast exp: pure FMA/ALU pipe (avoids MUFU throughput wall: 33.5M exps).
// exp(x) = 2^(x*log2e); 2^f via degree-5 poly on [-0.5,0.5], exponent via
// bit splice. |rel err| ~ 2.4e-6, far inside the 1e-3 budget.
// ---------------------------------------------------------------------------
__device__ __forceinline__ float fast_exp(float x) {
    x = fmaxf(x, -87.0f);
    float z  = x * 1.4426950408889634f;
    float nf = z + 12582912.0f;                    // 1.5 * 2^23 round trick
    int   ei = __float_as_int(nf) - 0x4B400000;    // n as int (works for neg)
    float n  = nf - 12582912.0f;
    float f  = z - n;                              // [-0.5, 0.5]
    float p  =        1.3333558146e-3f;
    p = fmaf(p, f,    9.6181291e-3f);
    p = fmaf(p, f,    5.5504108664e-2f);
    p = fmaf(p, f,    2.4022650696e-1f);
    p = fmaf(p, f,    6.9314718056e-1f);
    p = fmaf(p, f,    1.0f);
    return __int_as_float(__float_as_int(p) + (ei << 23));
}

// ---------------------------------------------------------------------------
// Generic tiled SGEMM: C[z] = alpha * A[z] @ op(B[z]) (+ bias)
//   tile 128x128, K-step 16, 256 threads, 8x8 per-thread microtile.
//   TRANSB: B stored [N,K] row-major (computes A @ B^T)  — used for Q K^T.
//   blockIdx.z walks (A,B,C) by the given element strides: used for batching
//   AND for split-K (strides step through K, C strides to partial slabs).
// ---------------------------------------------------------------------------
template<bool TRANSB, bool BIAS>
__global__ void __launch_bounds__(256)
sgemm_kernel(const float* __restrict__ A, const float* __restrict__ Bm,
             float* __restrict__ C, const float* __restrict__ bias,
             int M, int N, int K, int lda, int ldb, int ldc, float alpha,
             long long sA, long long sB, long long sC)
{
    __shared__ float As[16][132];
    __shared__ float Bs[16][132];

    const int tid = threadIdx.x;
    const int tx = tid & 15, ty = tid >> 4;
    const int m0 = blockIdx.y * 128, n0 = blockIdx.x * 128;

    A  += (long long)blockIdx.z * sA;
    Bm += (long long)blockIdx.z * sB;
    C  += (long long)blockIdx.z * sC;

    float acc[8][8];
#pragma unroll
    for (int i = 0; i < 8; i++)
#pragma unroll
        for (int j = 0; j < 8; j++) acc[i][j] = 0.0f;

    for (int k0 = 0; k0 < K; k0 += 16) {
        // ---- load A tile (transposed into smem) ----
#pragma unroll
        for (int i = 0; i < 2; i++) {
            int idx = tid + i * 256;           // 0..511
            int m   = idx >> 2;                // 0..127
            int kq  = (idx & 3) << 2;          // 0,4,8,12
            float4 v = *reinterpret_cast<const float4*>(
                A + (long long)(m0 + m) * lda + (k0 + kq));
            As[kq + 0][m] = v.x; As[kq + 1][m] = v.y;
            As[kq + 2][m] = v.z; As[kq + 3][m] = v.w;
        }
        // ---- load B tile ----
        if (TRANSB) {
#pragma unroll
            for (int i = 0; i < 2; i++) {
                int idx = tid + i * 256;
                int n   = idx >> 2;
                int kq  = (idx & 3) << 2;
                float4 v = *reinterpret_cast<const float4*>(
                    Bm + (long long)(n0 + n) * ldb + (k0 + kq));
                Bs[kq + 0][n] = v.x; Bs[kq + 1][n] = v.y;
                Bs[kq + 2][n] = v.z; Bs[kq + 3][n] = v.w;
            }
        } else {
#pragma unroll
            for (int i = 0; i < 2; i++) {
                int idx = tid + i * 256;
                int k   = idx >> 5;            // 0..15
                int nq  = (idx & 31) << 2;     // 0..124
                float4 v = *reinterpret_cast<const float4*>(
                    Bm + (long long)(k0 + k) * ldb + (n0 + nq));
                *reinterpret_cast<float4*>(&Bs[k][nq]) = v;
            }
        }
        __syncthreads();

        // ---- compute: split fragments (ty*4 | 64+ty*4) for conflict-free LDS.128
#pragma unroll
        for (int kk = 0; kk < 16; kk++) {
            float4 va0 = *reinterpret_cast<const float4*>(&As[kk][ty * 4]);
            float4 va1 = *reinterpret_cast<const float4*>(&As[kk][64 + ty * 4]);
            float4 vb0 = *reinterpret_cast<const float4*>(&Bs[kk][tx * 4]);
            float4 vb1 = *reinterpret_cast<const float4*>(&Bs[kk][64 + tx * 4]);
            float a[8] = {va0.x, va0.y, va0.z, va0.w, va1.x, va1.y, va1.z, va1.w};
            float b[8] = {vb0.x, vb0.y, vb0.z, vb0.w, vb1.x, vb1.y, vb1.z, vb1.w};
#pragma unroll
            for (int i = 0; i < 8; i++)
#pragma unroll
                for (int j = 0; j < 8; j++)
                    acc[i][j] = fmaf(a[i], b[j], acc[i][j]);
        }
        __syncthreads();
    }

    // ---- epilogue ----
#pragma unroll
    for (int i = 0; i < 8; i++) {
        int m = m0 + ((i < 4) ? (ty * 4 + i) : (64 + ty * 4 + (i - 4)));
#pragma unroll
        for (int jh = 0; jh < 2; jh++) {
            int n = n0 + ((jh == 0) ? (tx * 4) : (64 + tx * 4));
            float4 r;
            r.x = alpha * acc[i][jh * 4 + 0];
            r.y = alpha * acc[i][jh * 4 + 1];
            r.z = alpha * acc[i][jh * 4 + 2];
            r.w = alpha * acc[i][jh * 4 + 3];
            if (BIAS) {
                r.x += bias[n + 0]; r.y += bias[n + 1];
                r.z += bias[n + 2]; r.w += bias[n + 3];
            }
            *reinterpret_cast<float4*>(C + (long long)m * ldc + n) = r;
        }
    }
}

// ---------------------------------------------------------------------------
// lambda = exp(sum lq1*lk1) - exp(sum lq2*lk2) + (0.8 - 0.6*exp(-0.3*layer))
// ---------------------------------------------------------------------------
__global__ void lam_kernel(const float* __restrict__ lq1, const float* __restrict__ lk1,
                           const float* __restrict__ lq2, const float* __restrict__ lk2)
{
    int t = threadIdx.x;  // 32 threads
    float a = lq1[t] * lk1[t] + lq1[t + 32] * lk1[t + 32];
    float b = lq2[t] * lk2[t] + lq2[t + 32] * lk2[t + 32];
#pragma unroll
    for (int o = 16; o > 0; o >>= 1) {
        a += __shfl_down_sync(0xFFFFFFFFu, a, o);
        b += __shfl_down_sync(0xFFFFFFFFu, b, o);
    }
    if (t == 0)
        g_lam = expf(a) - expf(b) + (0.8f - 0.6f * expf(-0.3f * 0.0f));
}

// ---------------------------------------------------------------------------
// bv @ Wo partials (grid (2,64): 512 cols x 64 K-chunks of 128)
// ---------------------------------------------------------------------------
__global__ void bvo_partial_kernel(const float* __restrict__ bv,
                                   const float* __restrict__ Wo)
{
    int j  = blockIdx.x * 256 + threadIdx.x;   // 0..511
    int k0 = blockIdx.y * 128;
    float s = 0.0f;
#pragma unroll 4
    for (int k = k0; k < k0 + 128; k++)
        s = fmaf(bv[k], Wo[(long long)k * 512 + j], s);
    g_bfp[blockIdx.y * 512 + j] = s;
}

__global__ void bfin_kernel(const float* __restrict__ bo)
{
    int j = blockIdx.x * 256 + threadIdx.x;
    float s = 0.0f;
#pragma unroll
    for (int z = 0; z < 64; z++) s += g_bfp[z * 512 + j];
    g_bfin[j] = fmaf(1.0f - g_lam, s, bo[j]);
}

// ---------------------------------------------------------------------------
// Reduce the split-K partial slabs of W2
// ---------------------------------------------------------------------------
__global__ void w2_reduce_kernel()
{
    int i = blockIdx.x * 256 + threadIdx.x;    // 0..262143
    float s = 0.0f;
#pragma unroll
    for (int z = 0; z < W2_SPLITS; z++) s += g_W2p[(long long)z * 262144 + i];
    g_W2[i] = s;
}

// ---------------------------------------------------------------------------
// Row-wise softmax of P1 and P2, write diff = sm1 - lam*sm2 into P1.
// One block (256 thr) per row; exp values staged back into P to avoid
// recomputation (exp via FMA-pipe fast_exp).
// ---------------------------------------------------------------------------
__device__ __forceinline__ float block_reduce_max(float v, float* red) {
    int t = threadIdx.x;
    red[t] = v; __syncthreads();
#pragma unroll
    for (int s = 128; s > 0; s >>= 1) {
        if (t < s) red[t] = fmaxf(red[t], red[t + s]);
        __syncthreads();
    }
    float r = red[0]; __syncthreads();
    return r;
}

__device__ __forceinline__ float block_reduce_sum(float v, float* red) {
    int t = threadIdx.x;
    red[t] = v; __syncthreads();
#pragma unroll
    for (int s = 128; s > 0; s >>= 1) {
        if (t < s) red[t] += red[t + s];
        __syncthreads();
    }
    float r = red[0]; __syncthreads();
    return r;
}

__global__ void __launch_bounds__(256)
softmax_diff_kernel(float* __restrict__ P1, float* __restrict__ P2, int Slen)
{
    __shared__ float red[256];
    const int row = blockIdx.x;
    float* p1 = P1 + (long long)row * Slen;
    float* p2 = P2 + (long long)row * Slen;
    const int t = threadIdx.x;

    float m1 = -1e30f, m2 = -1e30f;
    for (int i = t; i < Slen; i += 256) {
        m1 = fmaxf(m1, p1[i]);
        m2 = fmaxf(m2, p2[i]);
    }
    float M1 = block_reduce_max(m1, red);
    float M2 = block_reduce_max(m2, red);

    float a1 = 0.0f, a2 = 0.0f;
    for (int i = t; i < Slen; i += 256) {
        float e1 = fast_exp(p1[i] - M1); p1[i] = e1; a1 += e1;
        float e2 = fast_exp(p2[i] - M2); p2[i] = e2; a2 += e2;
    }
    float S1 = block_reduce_sum(a1, red);
    float S2 = block_reduce_sum(a2, red);

    float c1 = 1.0f / S1;
    float c2 = g_lam / S2;
    for (int i = t; i < Slen; i += 256)
        p1[i] = p1[i] * c1 - p2[i] * c2;
}

// ---------------------------------------------------------------------------
// Host orchestration
// ---------------------------------------------------------------------------
extern "C" void kernel_launch(void* const* d_in, const int* in_sizes, int n_in,
                              void* d_out, int out_size)
{
    const float* x    = (const float*)d_in[0];
    const float* Wqkv = (const float*)d_in[1];
    const float* bqkv = (const float*)d_in[2];
    const float* Wv   = (const float*)d_in[3];
    const float* bv   = (const float*)d_in[4];
    const float* Wo   = (const float*)d_in[5];
    const float* bo   = (const float*)d_in[6];
    const float* lq1  = (const float*)d_in[7];
    const float* lk1  = (const float*)d_in[8];
    const float* lq2  = (const float*)d_in[9];
    const float* lk2  = (const float*)d_in[10];
    float* out = (float*)d_out;

    float *qkv, *P1, *P2, *tbuf, *W2p, *W2, *bfin;
    cudaGetSymbolAddress((void**)&qkv,  g_qkv);
    cudaGetSymbolAddress((void**)&P1,   g_P1);
    cudaGetSymbolAddress((void**)&P2,   g_P2);
    cudaGetSymbolAddress((void**)&tbuf, g_t);
    cudaGetSymbolAddress((void**)&W2p,  g_W2p);
    cudaGetSymbolAddress((void**)&W2,   g_W2);
    cudaGetSymbolAddress((void**)&bfin, g_bfin);

    const long long PS = (long long)SEQ * SEQ;          // 2048*2048
    const long long QS = (long long)SEQ * 1024;         // qkv batch stride
    const long long XS = (long long)SEQ * DMODEL;       // x / t batch stride

    // 1) lambda
    lam_kernel<<<1, 32>>>(lq1, lk1, lq2, lk2);

    // 2) combined output bias: (1-lam)*(bv@Wo) + bo
    bvo_partial_kernel<<<dim3(2, 64), 256>>>(bv, Wo);
    bfin_kernel<<<2, 256>>>(bo);

    // 3) qkv = x @ Wqkv + bqkv   [4096,512]@[512,1024]
    sgemm_kernel<false, true><<<dim3(1024 / 128, 4096 / 128, 1), 256>>>(
        x, Wqkv, qkv, bqkv, 4096, 1024, 512, 512, 1024, 1024, 1.0f, 0, 0, 0);

    // 4) logits: P1 = 0.125 * Q1 @ K1^T, P2 = 0.125 * Q2 @ K2^T  (per batch via z)
    sgemm_kernel<true, false><<<dim3(16, 16, BATCH), 256>>>(
        qkv + 0,   qkv + 512, P1, nullptr, SEQ, SEQ, 256, 1024, 1024, SEQ,
        0.125f, QS, QS, PS);
    sgemm_kernel<true, false><<<dim3(16, 16, BATCH), 256>>>(
        qkv + 256, qkv + 768, P2, nullptr, SEQ, SEQ, 256, 1024, 1024, SEQ,
        0.125f, QS, QS, PS);

    // 5) diff = softmax(P1) - lam * softmax(P2)  (into P1)
    softmax_diff_kernel<<<BATCH * SEQ, 256>>>(P1, P2, SEQ);

    // 6) t = diff @ x   [2048,2048]@[2048,512] per batch
    sgemm_kernel<false, false><<<dim3(512 / 128, SEQ / 128, BATCH), 256>>>(
        P1, x, tbuf, nullptr, SEQ, 512, SEQ, SEQ, 512, 512, 1.0f, PS, XS, XS);

    // 7) W2 = Wv @ Wo   [512,8192]@[8192,512], split-K x8 via z-strides
    sgemm_kernel<false, false><<<dim3(4, 4, W2_SPLITS), 256>>>(
        Wv, Wo, W2p, nullptr, 512, 512, 8192 / W2_SPLITS, 8192, 512, 512, 1.0f,
        8192 / W2_SPLITS, (long long)(8192 / W2_SPLITS) * 512, 512LL * 512);
    w2_reduce_kernel<<<1024, 256>>>();

    // 8) out = t @ W2 + bfin   [4096,512]@[512,512]
    sgemm_kernel<false, true><<<dim3(4, 32, 1), 256>>>(
        tbuf, W2, out, bfin, 4096, 512, 512, 512, 512, 512, 1.0f, 0, 0, 0);
}

// round 5
// speedup vs baseline: 1.5970x; 1.5970x over previous
#include <cuda_runtime.h>
#include <cuda_bf16.h>
#include <stdint.h>

// ============================================================================
// DifferentialAttention — round 5: identical to round-4 HMMA design
// (round 4 never ran: GB300 container infra failure; design re-audited,
// fragment maps / strides verified, resubmitted unchanged)
//
//  out = diff @ x @ (Wv@Wo) + (1-lam)*(bv@Wo) + bo
//  diff = softmax(Q1K1^T/8) - lam*softmax(Q2K2^T/8); exp fused into logits
//  GEMM epilogue (no max-sub; logits bounded), normalization folded:
//  t = (1/S1) o (E1@x) - (lam/S2) o (E2@x)
//
//  GEMM core: mma.sync.m16n8k16 bf16->fp32, bf16 hi/lo 3-split (hh+lh+hl,
//  error ~2^-16), 128x128 tile, K-chunk 32, 8 warps, cp.async double buffer.
// ============================================================================

#define SEQ 2048

// ---------------------------------------------------------------------------
// Scratch (device globals)
// ---------------------------------------------------------------------------
__device__ __align__(16) float g_qkv[4096 * 1024];
__device__ __align__(16) __nv_bfloat16 g_qkvh[4096 * 1024];
__device__ __align__(16) __nv_bfloat16 g_qkvl[4096 * 1024];
__device__ __align__(16) __nv_bfloat16 g_xh[4096 * 512];
__device__ __align__(16) __nv_bfloat16 g_xl[4096 * 512];
__device__ __align__(16) __nv_bfloat16 g_xTh[2 * 512 * 2048];
__device__ __align__(16) __nv_bfloat16 g_xTl[2 * 512 * 2048];
__device__ __align__(16) __nv_bfloat16 g_wqTh[1024 * 512];
__device__ __align__(16) __nv_bfloat16 g_wqTl[1024 * 512];
__device__ __align__(16) __nv_bfloat16 g_woTh[512 * 8192];
__device__ __align__(16) __nv_bfloat16 g_woTl[512 * 8192];
__device__ __align__(16) __nv_bfloat16 g_wvh[512 * 8192];
__device__ __align__(16) __nv_bfloat16 g_wvl[512 * 8192];
__device__ __align__(16) __nv_bfloat16 g_Eh[2LL * 2 * 2048 * 2048]; // [map][b][S][S]
__device__ __align__(16) __nv_bfloat16 g_El[2LL * 2 * 2048 * 2048];
__device__ float g_S[2 * 4096];                            // rowsums [map][b*S+r]
__device__ __align__(16) float g_u[2LL * 2 * 2048 * 512];  // [map][b][S][512]
__device__ __align__(16) __nv_bfloat16 g_th[4096 * 512];
__device__ __align__(16) __nv_bfloat16 g_tl[4096 * 512];
__device__ __align__(16) float g_W2p[8 * 512 * 512];
__device__ __align__(16) __nv_bfloat16 g_w2Th[512 * 512];
__device__ __align__(16) __nv_bfloat16 g_w2Tl[512 * 512];
__device__ float g_bfp[64 * 512];
__device__ float g_bfin[512];
__device__ float g_lam;

// ---------------------------------------------------------------------------
// PTX helpers (sm_80-era, valid on base sm_100)
// ---------------------------------------------------------------------------
__device__ __forceinline__ uint32_t smem_u32(const void* p) {
    uint32_t a;
    asm("{ .reg .u64 t; cvta.to.shared.u64 t, %1; cvt.u32.u64 %0, t; }"
        : "=r"(a) : "l"(p));
    return a;
}
__device__ __forceinline__ void cp16(uint32_t s, const void* g) {
    asm volatile("cp.async.cg.shared.global [%0], [%1], 16;" :: "r"(s), "l"(g));
}
#define CP_COMMIT() asm volatile("cp.async.commit_group;")
#define CP_WAIT(n)  asm volatile("cp.async.wait_group %0;" :: "n"(n))

__device__ __forceinline__ void ldsm_x4(uint32_t* r, uint32_t a) {
    asm volatile("ldmatrix.sync.aligned.m8n8.x4.shared.b16 {%0,%1,%2,%3}, [%4];"
                 : "=r"(r[0]), "=r"(r[1]), "=r"(r[2]), "=r"(r[3]) : "r"(a));
}
__device__ __forceinline__ void ldsm_x2(uint32_t* r, uint32_t a) {
    asm volatile("ldmatrix.sync.aligned.m8n8.x2.shared.b16 {%0,%1}, [%2];"
                 : "=r"(r[0]), "=r"(r[1]) : "r"(a));
}
__device__ __forceinline__ void mma16816(float* c, const uint32_t* a, const uint32_t* b) {
    asm volatile("mma.sync.aligned.m16n8k16.row.col.f32.bf16.bf16.f32 "
                 "{%0,%1,%2,%3}, {%4,%5,%6,%7}, {%8,%9}, {%0,%1,%2,%3};"
                 : "+f"(c[0]), "+f"(c[1]), "+f"(c[2]), "+f"(c[3])
                 : "r"(a[0]), "r"(a[1]), "r"(a[2]), "r"(a[3]), "r"(b[0]), "r"(b[1]));
}

// ---------------------------------------------------------------------------
// fast exp (FMA pipe, rel err ~2.4e-6)
// ---------------------------------------------------------------------------
__device__ __forceinline__ float fast_exp(float x) {
    x = fmaxf(x, -87.0f);
    float z  = x * 1.4426950408889634f;
    float nf = z + 12582912.0f;
    int   ei = __float_as_int(nf) - 0x4B400000;
    float f  = z - (nf - 12582912.0f);
    float p  =        1.3333558146e-3f;
    p = fmaf(p, f,    9.6181291e-3f);
    p = fmaf(p, f,    5.5504108664e-2f);
    p = fmaf(p, f,    2.4022650696e-1f);
    p = fmaf(p, f,    6.9314718056e-1f);
    p = fmaf(p, f,    1.0f);
    return __int_as_float(__float_as_int(p) + (ei << 23));
}
__device__ __forceinline__ uint32_t pack_bf2(__nv_bfloat16 a, __nv_bfloat16 b) {
    return (uint32_t)__bfloat16_as_ushort(a) | ((uint32_t)__bfloat16_as_ushort(b) << 16);
}

// ---------------------------------------------------------------------------
// HMMA GEMM: C = A @ B^T, A [M,K] hi/lo bf16 row-major, B [N,K] hi/lo.
// Block 128x128, K-chunk 32, 8 warps (2 M x 4 N), warp tile 64x32.
// 3-split per k16: Ah*Bh + Al*Bh + Ah*Bl (fp32 accum).
// MODE 0: C fp32.  MODE 1: + bias[n].  MODE 2: exp epilogue -> Eh/El bf16
// planes + atomicAdd rowsums. z walks A/B/C/rowsum by element strides.
// Smem stage: 4 planes x (128 rows x 80B pitch) = 40960 B; 2 stages.
// ---------------------------------------------------------------------------
#define PITCH 80
#define PLANE_BYTES (128 * PITCH)       // 10240
#define STAGE_BYTES (4 * PLANE_BYTES)   // 40960

template<int MODE>
__global__ void __launch_bounds__(256)
hmma_gemm(const __nv_bfloat16* __restrict__ Ah, const __nv_bfloat16* __restrict__ Al,
          const __nv_bfloat16* __restrict__ Bh, const __nv_bfloat16* __restrict__ Bl,
          float* __restrict__ C, const float* __restrict__ bias,
          __nv_bfloat16* __restrict__ Eh, __nv_bfloat16* __restrict__ El,
          float* __restrict__ rowsum,
          int K, int lda, int ldb, int ldc,
          long long sA, long long sB, long long sC, long long sR)
{
    extern __shared__ __align__(16) char smem[];
    const uint32_t sb = smem_u32(smem);

    const int tid = threadIdx.x;
    const int lane = tid & 31, wid = tid >> 5;
    const int wm = wid & 1, wn = wid >> 1;
    const int m0 = blockIdx.y * 128, n0 = blockIdx.x * 128;
    const long long zA = (long long)blockIdx.z * sA;
    const long long zB = (long long)blockIdx.z * sB;
    Ah += zA; Al += zA; Bh += zB; Bl += zB;

    // loader: 64 threads per plane (0 Ahi, 1 Alo, 2 Bhi, 3 Blo)
    const int tsel = tid >> 6;
    const __nv_bfloat16* gbase =
        (tsel == 0) ? Ah : (tsel == 1) ? Al : (tsel == 2) ? Bh : Bl;
    const int row0 = (tsel < 2) ? m0 : n0;
    const int ld   = (tsel < 2) ? lda : ldb;
    const int r64  = tid & 63;
    const uint32_t plane_off = (uint32_t)tsel * PLANE_BYTES;

    const int nch = K >> 5;

#define LOAD_CHUNK(buf, k0) do { \
    uint32_t st_ = sb + (buf) * STAGE_BYTES + plane_off; \
    _Pragma("unroll") \
    for (int it_ = 0; it_ < 8; it_++) { \
        int idx_ = r64 + it_ * 64; \
        int row_ = idx_ >> 2, seg_ = idx_ & 3; \
        const __nv_bfloat16* g_ = gbase + (long long)(row0 + row_) * ld + (k0) + seg_ * 8; \
        cp16(st_ + row_ * PITCH + seg_ * 16, g_); \
    } \
    CP_COMMIT(); \
} while (0)

    LOAD_CHUNK(0, 0);

    float c[4][4][4];
#pragma unroll
    for (int a = 0; a < 4; a++)
#pragma unroll
        for (int b = 0; b < 4; b++)
#pragma unroll
            for (int q = 0; q < 4; q++) c[a][b][q] = 0.0f;

    for (int i = 0; i < nch; i++) {
        if (i + 1 < nch) {
            LOAD_CHUNK((i + 1) & 1, (i + 1) * 32);
            CP_WAIT(1);
        } else {
            CP_WAIT(0);
        }
        __syncthreads();

        const uint32_t stg = sb + (i & 1) * STAGE_BYTES;
        const uint32_t a_row_off = (uint32_t)(wm * 64 + (lane & 15)) * PITCH + (lane >> 4) * 16;
        const uint32_t b_row_off = (uint32_t)(wn * 32 + (lane & 7)) * PITCH + ((lane >> 3) & 1) * 16;

#pragma unroll
        for (int k16 = 0; k16 < 2; k16++) {
            uint32_t ah[4][4], al[4][4], bh[4][2], bl[4][2];
            const uint32_t ko = k16 * 32;
#pragma unroll
            for (int tm = 0; tm < 4; tm++) {
                ldsm_x4(ah[tm], stg + 0 * PLANE_BYTES + tm * 16 * PITCH + a_row_off + ko);
                ldsm_x4(al[tm], stg + 1 * PLANE_BYTES + tm * 16 * PITCH + a_row_off + ko);
            }
#pragma unroll
            for (int tn = 0; tn < 4; tn++) {
                ldsm_x2(bh[tn], stg + 2 * PLANE_BYTES + tn * 8 * PITCH + b_row_off + ko);
                ldsm_x2(bl[tn], stg + 3 * PLANE_BYTES + tn * 8 * PITCH + b_row_off + ko);
            }
#pragma unroll
            for (int tm = 0; tm < 4; tm++)
#pragma unroll
                for (int tn = 0; tn < 4; tn++) {
                    mma16816(c[tm][tn], ah[tm], bh[tn]);
                    mma16816(c[tm][tn], al[tm], bh[tn]);
                    mma16816(c[tm][tn], ah[tm], bl[tn]);
                }
        }
        __syncthreads();
    }
#undef LOAD_CHUNK

    // ------------------ epilogue ------------------
    // c[tm][tn][{0,1}] -> row r0 = m0+wm*64+tm*16+(lane>>2),   col+{0,1}
    // c[tm][tn][{2,3}] -> row r0+8
    // col = n0 + wn*32 + tn*8 + (lane&3)*2
    if (MODE == 2) {
#pragma unroll
        for (int tm = 0; tm < 4; tm++) {
            const int r0 = m0 + wm * 64 + tm * 16 + (lane >> 2);
            float s0 = 0.0f, s1 = 0.0f;
#pragma unroll
            for (int tn = 0; tn < 4; tn++) {
                const int col = n0 + wn * 32 + tn * 8 + (lane & 3) * 2;
                float e0 = fast_exp(c[tm][tn][0]);
                float e1 = fast_exp(c[tm][tn][1]);
                float e2 = fast_exp(c[tm][tn][2]);
                float e3 = fast_exp(c[tm][tn][3]);
                s0 += e0 + e1; s1 += e2 + e3;
                __nv_bfloat16 h0 = __float2bfloat16(e0), h1 = __float2bfloat16(e1);
                __nv_bfloat16 h2 = __float2bfloat16(e2), h3 = __float2bfloat16(e3);
                __nv_bfloat16 l0 = __float2bfloat16(e0 - __bfloat162float(h0));
                __nv_bfloat16 l1 = __float2bfloat16(e1 - __bfloat162float(h1));
                __nv_bfloat16 l2 = __float2bfloat16(e2 - __bfloat162float(h2));
                __nv_bfloat16 l3 = __float2bfloat16(e3 - __bfloat162float(h3));
                long long o0 = (long long)blockIdx.z * sC + (long long)r0 * ldc + col;
                long long o1 = o0 + 8LL * ldc;
                *reinterpret_cast<uint32_t*>(Eh + o0) = pack_bf2(h0, h1);
                *reinterpret_cast<uint32_t*>(El + o0) = pack_bf2(l0, l1);
                *reinterpret_cast<uint32_t*>(Eh + o1) = pack_bf2(h2, h3);
                *reinterpret_cast<uint32_t*>(El + o1) = pack_bf2(l2, l3);
            }
            // reduce over the 4 lanes sharing this row (lane&3 group)
            s0 += __shfl_xor_sync(0xFFFFFFFFu, s0, 1);
            s0 += __shfl_xor_sync(0xFFFFFFFFu, s0, 2);
            s1 += __shfl_xor_sync(0xFFFFFFFFu, s1, 1);
            s1 += __shfl_xor_sync(0xFFFFFFFFu, s1, 2);
            if ((lane & 3) == 0) {
                atomicAdd(rowsum + blockIdx.z * sR + r0, s0);
                atomicAdd(rowsum + blockIdx.z * sR + r0 + 8, s1);
            }
        }
    } else {
#pragma unroll
        for (int tm = 0; tm < 4; tm++) {
            const int r0 = m0 + wm * 64 + tm * 16 + (lane >> 2);
#pragma unroll
            for (int tn = 0; tn < 4; tn++) {
                const int col = n0 + wn * 32 + tn * 8 + (lane & 3) * 2;
                float2 v0 = make_float2(c[tm][tn][0], c[tm][tn][1]);
                float2 v1 = make_float2(c[tm][tn][2], c[tm][tn][3]);
                if (MODE == 1) {
                    v0.x += bias[col]; v0.y += bias[col + 1];
                    v1.x += bias[col]; v1.y += bias[col + 1];
                }
                long long o0 = (long long)blockIdx.z * sC + (long long)r0 * ldc + col;
                *reinterpret_cast<float2*>(C + o0) = v0;
                *reinterpret_cast<float2*>(C + o0 + 8LL * ldc) = v1;
            }
        }
    }
}

// ---------------------------------------------------------------------------
// small kernels
// ---------------------------------------------------------------------------
__global__ void lam_kernel(const float* __restrict__ lq1, const float* __restrict__ lk1,
                           const float* __restrict__ lq2, const float* __restrict__ lk2)
{
    int t = threadIdx.x;
    float a = lq1[t] * lk1[t] + lq1[t + 32] * lk1[t + 32];
    float b = lq2[t] * lk2[t] + lq2[t + 32] * lk2[t + 32];
#pragma unroll
    for (int o = 16; o > 0; o >>= 1) {
        a += __shfl_down_sync(0xFFFFFFFFu, a, o);
        b += __shfl_down_sync(0xFFFFFFFFu, b, o);
    }
    if (t == 0)
        g_lam = expf(a) - expf(b) + (0.8f - 0.6f);
}

__global__ void bvo_partial_kernel(const float* __restrict__ bv, const float* __restrict__ Wo)
{
    int j  = blockIdx.x * 256 + threadIdx.x;
    int k0 = blockIdx.y * 128;
    float s = 0.0f;
#pragma unroll 4
    for (int k = k0; k < k0 + 128; k++)
        s = fmaf(bv[k], Wo[(long long)k * 512 + j], s);
    g_bfp[blockIdx.y * 512 + j] = s;
}

__global__ void bfin_kernel(const float* __restrict__ bo)
{
    int j = blockIdx.x * 256 + threadIdx.x;
    float s = 0.0f;
#pragma unroll
    for (int z = 0; z < 64; z++) s += g_bfp[z * 512 + j];
    g_bfin[j] = fmaf(1.0f - g_lam, s, bo[j]);
}

__global__ void zero_S_kernel() { g_S[blockIdx.x * 256 + threadIdx.x] = 0.0f; }

// fp32 -> bf16 hi/lo (optionally scale first qcols of each row by `scale`)
__global__ void conv_plain(const float* __restrict__ src,
                           __nv_bfloat16* __restrict__ hi, __nv_bfloat16* __restrict__ lo,
                           long long n, int ldm, int qcols, float scale)
{
    long long i = (long long)blockIdx.x * 256 + threadIdx.x;
    if (i >= n) return;
    float v = src[i];
    if (qcols && (int)(i % ldm) < qcols) v *= scale;
    __nv_bfloat16 h = __float2bfloat16(v);
    hi[i] = h;
    lo[i] = __float2bfloat16(v - __bfloat162float(h));
}

// transpose fp32 [R,C] -> bf16 hi/lo [C,R]
__global__ void conv_trans(const float* __restrict__ src,
                           __nv_bfloat16* __restrict__ dh, __nv_bfloat16* __restrict__ dl,
                           int R, int C, long long sSrc, long long sDst)
{
    __shared__ float tile[32][33];
    src += (long long)blockIdx.z * sSrc;
    dh  += (long long)blockIdx.z * sDst;
    dl  += (long long)blockIdx.z * sDst;
    int c0 = blockIdx.x * 32, r0 = blockIdx.y * 32;
    int tx = threadIdx.x, ty = threadIdx.y;
#pragma unroll
    for (int j = 0; j < 32; j += 8)
        tile[ty + j][tx] = src[(long long)(r0 + ty + j) * C + c0 + tx];
    __syncthreads();
#pragma unroll
    for (int j = 0; j < 32; j += 8) {
        float v = tile[tx][ty + j];
        long long o = (long long)(c0 + ty + j) * R + r0 + tx;
        __nv_bfloat16 h = __float2bfloat16(v);
        dh[o] = h;
        dl[o] = __float2bfloat16(v - __bfloat162float(h));
    }
}

// t = (1/S1) o u1 - (lam/S2) o u2  -> bf16 hi/lo
__global__ void combine_kernel()
{
    long long i = (long long)blockIdx.x * 256 + threadIdx.x;   // over 4096*512
    int row = (int)(i >> 9);
    float c1 = 1.0f / g_S[row];
    float c2 = g_lam / g_S[4096 + row];
    float v = c1 * g_u[i] - c2 * g_u[i + 2097152];
    __nv_bfloat16 h = __float2bfloat16(v);
    g_th[i] = h;
    g_tl[i] = __float2bfloat16(v - __bfloat162float(h));
}

// reduce 8 split-K slabs of W2^T -> bf16 hi/lo
__global__ void w2_reduce_conv()
{
    int i = blockIdx.x * 256 + threadIdx.x;   // 0..262143
    float s = 0.0f;
#pragma unroll
    for (int z = 0; z < 8; z++) s += g_W2p[(long long)z * 262144 + i];
    __nv_bfloat16 h = __float2bfloat16(s);
    g_w2Th[i] = h;
    g_w2Tl[i] = __float2bfloat16(s - __bfloat162float(h));
}

// ---------------------------------------------------------------------------
// Host orchestration
// ---------------------------------------------------------------------------
extern "C" void kernel_launch(void* const* d_in, const int* in_sizes, int n_in,
                              void* d_out, int out_size)
{
    const float* x    = (const float*)d_in[0];
    const float* Wqkv = (const float*)d_in[1];
    const float* bqkv = (const float*)d_in[2];
    const float* Wv   = (const float*)d_in[3];
    const float* bv   = (const float*)d_in[4];
    const float* Wo   = (const float*)d_in[5];
    const float* bo   = (const float*)d_in[6];
    const float* lq1  = (const float*)d_in[7];
    const float* lk1  = (const float*)d_in[8];
    const float* lq2  = (const float*)d_in[9];
    const float* lk2  = (const float*)d_in[10];
    float* out = (float*)d_out;

    const int SMEM = 2 * STAGE_BYTES;   // 81920
    cudaFuncSetAttribute(hmma_gemm<0>, cudaFuncAttributeMaxDynamicSharedMemorySize, SMEM);
    cudaFuncSetAttribute(hmma_gemm<1>, cudaFuncAttributeMaxDynamicSharedMemorySize, SMEM);
    cudaFuncSetAttribute(hmma_gemm<2>, cudaFuncAttributeMaxDynamicSharedMemorySize, SMEM);

#define SYM(v, s) cudaGetSymbolAddress((void**)&v, s)
    float *qkv, *W2p, *S, *u, *bfin;
    __nv_bfloat16 *qkvh, *qkvl, *xh, *xl, *xTh, *xTl, *wqTh, *wqTl;
    __nv_bfloat16 *woTh, *woTl, *wvh, *wvl, *Ehp, *Elp, *th, *tl, *w2Th, *w2Tl;
    SYM(qkv, g_qkv); SYM(W2p, g_W2p); SYM(S, g_S); SYM(u, g_u); SYM(bfin, g_bfin);
    SYM(qkvh, g_qkvh); SYM(qkvl, g_qkvl); SYM(xh, g_xh); SYM(xl, g_xl);
    SYM(xTh, g_xTh); SYM(xTl, g_xTl); SYM(wqTh, g_wqTh); SYM(wqTl, g_wqTl);
    SYM(woTh, g_woTh); SYM(woTl, g_woTl); SYM(wvh, g_wvh); SYM(wvl, g_wvl);
    SYM(Ehp, g_Eh); SYM(Elp, g_El); SYM(th, g_th); SYM(tl, g_tl);
    SYM(w2Th, g_w2Th); SYM(w2Tl, g_w2Tl);
#undef SYM

    const long long PS = 2048LL * 2048;

    // small prep
    lam_kernel<<<1, 32>>>(lq1, lk1, lq2, lk2);
    bvo_partial_kernel<<<dim3(2, 64), 256>>>(bv, Wo);
    bfin_kernel<<<2, 256>>>(bo);
    zero_S_kernel<<<32, 256>>>();

    // conversions
    conv_plain<<<(4096 * 512) / 256, 256>>>(x, xh, xl, 4096LL * 512, 512, 0, 1.0f);
    conv_trans<<<dim3(16, 64, 2), dim3(32, 8)>>>(x, xTh, xTl, 2048, 512,
                                                 2048LL * 512, 512LL * 2048);
    conv_trans<<<dim3(32, 16, 1), dim3(32, 8)>>>(Wqkv, wqTh, wqTl, 512, 1024, 0, 0);
    conv_trans<<<dim3(16, 256, 1), dim3(32, 8)>>>(Wo, woTh, woTl, 8192, 512, 0, 0);
    conv_plain<<<(512 * 8192) / 256, 256>>>(Wv, wvh, wvl, 512LL * 8192, 512, 0, 1.0f);

    // qkv = x @ Wqkv + bqkv   [4096,512]@[512,1024]
    hmma_gemm<1><<<dim3(8, 32, 1), 256, SMEM>>>(xh, xl, wqTh, wqTl, qkv, bqkv,
        nullptr, nullptr, nullptr, 512, 512, 512, 1024, 0, 0, 0, 0);
    // qkv -> bf16 hi/lo, Q cols (<512) scaled by 1/sqrt(64)
    conv_plain<<<(4096 * 1024) / 256, 256>>>(qkv, qkvh, qkvl, 4096LL * 1024, 1024, 512, 0.125f);

    // E_m = exp(Q_m @ K_m^T), rowsums (z = batch)
    hmma_gemm<2><<<dim3(16, 16, 2), 256, SMEM>>>(qkvh + 0, qkvl + 0, qkvh + 512, qkvl + 512,
        nullptr, nullptr, Ehp, Elp, S, 256, 1024, 1024, 2048,
        2048LL * 1024, 2048LL * 1024, PS, 2048);
    hmma_gemm<2><<<dim3(16, 16, 2), 256, SMEM>>>(qkvh + 256, qkvl + 256, qkvh + 768, qkvl + 768,
        nullptr, nullptr, Ehp + 2 * PS, Elp + 2 * PS, S + 4096, 256, 1024, 1024, 2048,
        2048LL * 1024, 2048LL * 1024, PS, 2048);

    // u_m = E_m @ x   (z = batch)
    hmma_gemm<0><<<dim3(4, 16, 2), 256, SMEM>>>(Ehp, Elp, xTh, xTl, u, nullptr,
        nullptr, nullptr, nullptr, 2048, 2048, 2048, 512,
        PS, 512LL * 2048, 2048LL * 512, 0);
    hmma_gemm<0><<<dim3(4, 16, 2), 256, SMEM>>>(Ehp + 2 * PS, Elp + 2 * PS, xTh, xTl,
        u + 2097152, nullptr, nullptr, nullptr, nullptr, 2048, 2048, 2048, 512,
        PS, 512LL * 2048, 2048LL * 512, 0);

    // t = c1 o u1 - c2 o u2 -> bf16 hi/lo
    combine_kernel<<<(4096 * 512) / 256, 256>>>();

    // W2^T = Wo^T @ Wv^T via split-K (z = 8 K-slabs of 1024), then reduce+convert
    hmma_gemm<0><<<dim3(4, 4, 8), 256, SMEM>>>(woTh, woTl, wvh, wvl, W2p, nullptr,
        nullptr, nullptr, nullptr, 1024, 8192, 8192, 512, 1024, 1024, 262144, 0);
    w2_reduce_conv<<<1024, 256>>>();

    // out = t @ W2 + bfin   [4096,512]@[512,512]
    hmma_gemm<1><<<dim3(4, 32, 1), 256, SMEM>>>(th, tl, w2Th, w2Tl, out, bfin,
        nullptr, nullptr, nullptr, 512, 512, 512, 512, 0, 0, 0, 0);
}

// round 7
// speedup vs baseline: 1.6407x; 1.0273x over previous
#include <cuda_runtime.h>
#include <cuda_bf16.h>
#include <stdint.h>

// ============================================================================
// DifferentialAttention — round 7: identical to round-6 (infra failure on
// round 6; design re-audited: z-strides, MODE3 zeroing/scaling verified)
//
//  out = diff @ x @ (Wv@Wo) + (1-lam)*(bv@Wo) + bo
//  diff = softmax(Q1K1^T/8) - lam*softmax(Q2K2^T/8); exp fused into logits
//  GEMM epilogue (no max-sub; logits bounded), normalization folded:
//  t = (1/S1) o (E1@x) - (lam/S2) o (E2@x)
//
//  vs round 5: qkv->bf16 conversion fused into qkv GEMM epilogue (MODE 3,
//  also zeroes rowsums), E1/E2 and u1/u2 merged into single launches via
//  z = (z1,z2) dual-stride decomposition, x conversions fused, small kernels
//  merged. 16 launches -> 12. GEMM core unchanged.
// ============================================================================

#define SEQ 2048

// ---------------------------------------------------------------------------
// Scratch (device globals)
// ---------------------------------------------------------------------------
__device__ __align__(16) __nv_bfloat16 g_qkvh[4096 * 1024];
__device__ __align__(16) __nv_bfloat16 g_qkvl[4096 * 1024];
__device__ __align__(16) __nv_bfloat16 g_xh[4096 * 512];
__device__ __align__(16) __nv_bfloat16 g_xl[4096 * 512];
__device__ __align__(16) __nv_bfloat16 g_xTh[2 * 512 * 2048];
__device__ __align__(16) __nv_bfloat16 g_xTl[2 * 512 * 2048];
__device__ __align__(16) __nv_bfloat16 g_wqTh[1024 * 512];
__device__ __align__(16) __nv_bfloat16 g_wqTl[1024 * 512];
__device__ __align__(16) __nv_bfloat16 g_woTh[512 * 8192];
__device__ __align__(16) __nv_bfloat16 g_woTl[512 * 8192];
__device__ __align__(16) __nv_bfloat16 g_wvh[512 * 8192];
__device__ __align__(16) __nv_bfloat16 g_wvl[512 * 8192];
__device__ __align__(16) __nv_bfloat16 g_Eh[2LL * 2 * 2048 * 2048]; // [map][b][S][S]
__device__ __align__(16) __nv_bfloat16 g_El[2LL * 2 * 2048 * 2048];
__device__ float g_S[2 * 4096];                            // rowsums [map][b*S+r]
__device__ __align__(16) float g_u[2LL * 2 * 2048 * 512];  // [map][b][S][512]
__device__ __align__(16) __nv_bfloat16 g_th[4096 * 512];
__device__ __align__(16) __nv_bfloat16 g_tl[4096 * 512];
__device__ __align__(16) float g_W2p[8 * 512 * 512];
__device__ __align__(16) __nv_bfloat16 g_w2Th[512 * 512];
__device__ __align__(16) __nv_bfloat16 g_w2Tl[512 * 512];
__device__ float g_bfp[64 * 512];
__device__ float g_bfin[512];
__device__ float g_lam;

// ---------------------------------------------------------------------------
// PTX helpers (sm_80-era, valid on base sm_100)
// ---------------------------------------------------------------------------
__device__ __forceinline__ uint32_t smem_u32(const void* p) {
    uint32_t a;
    asm("{ .reg .u64 t; cvta.to.shared.u64 t, %1; cvt.u32.u64 %0, t; }"
        : "=r"(a) : "l"(p));
    return a;
}
__device__ __forceinline__ void cp16(uint32_t s, const void* g) {
    asm volatile("cp.async.cg.shared.global [%0], [%1], 16;" :: "r"(s), "l"(g));
}
#define CP_COMMIT() asm volatile("cp.async.commit_group;")
#define CP_WAIT(n)  asm volatile("cp.async.wait_group %0;" :: "n"(n))

__device__ __forceinline__ void ldsm_x4(uint32_t* r, uint32_t a) {
    asm volatile("ldmatrix.sync.aligned.m8n8.x4.shared.b16 {%0,%1,%2,%3}, [%4];"
                 : "=r"(r[0]), "=r"(r[1]), "=r"(r[2]), "=r"(r[3]) : "r"(a));
}
__device__ __forceinline__ void ldsm_x2(uint32_t* r, uint32_t a) {
    asm volatile("ldmatrix.sync.aligned.m8n8.x2.shared.b16 {%0,%1}, [%2];"
                 : "=r"(r[0]), "=r"(r[1]) : "r"(a));
}
__device__ __forceinline__ void mma16816(float* c, const uint32_t* a, const uint32_t* b) {
    asm volatile("mma.sync.aligned.m16n8k16.row.col.f32.bf16.bf16.f32 "
                 "{%0,%1,%2,%3}, {%4,%5,%6,%7}, {%8,%9}, {%0,%1,%2,%3};"
                 : "+f"(c[0]), "+f"(c[1]), "+f"(c[2]), "+f"(c[3])
                 : "r"(a[0]), "r"(a[1]), "r"(a[2]), "r"(a[3]), "r"(b[0]), "r"(b[1]));
}

// ---------------------------------------------------------------------------
// fast exp (FMA pipe, rel err ~2.4e-6)
// ---------------------------------------------------------------------------
__device__ __forceinline__ float fast_exp(float x) {
    x = fmaxf(x, -87.0f);
    float z  = x * 1.4426950408889634f;
    float nf = z + 12582912.0f;
    int   ei = __float_as_int(nf) - 0x4B400000;
    float f  = z - (nf - 12582912.0f);
    float p  =        1.3333558146e-3f;
    p = fmaf(p, f,    9.6181291e-3f);
    p = fmaf(p, f,    5.5504108664e-2f);
    p = fmaf(p, f,    2.4022650696e-1f);
    p = fmaf(p, f,    6.9314718056e-1f);
    p = fmaf(p, f,    1.0f);
    return __int_as_float(__float_as_int(p) + (ei << 23));
}
__device__ __forceinline__ uint32_t pack_bf2(__nv_bfloat16 a, __nv_bfloat16 b) {
    return (uint32_t)__bfloat16_as_ushort(a) | ((uint32_t)__bfloat16_as_ushort(b) << 16);
}

// ---------------------------------------------------------------------------
// HMMA GEMM: C = A @ B^T, A [M,K] hi/lo bf16 row-major, B [N,K] hi/lo.
// Block 128x128, K-chunk 32, 8 warps (2 M x 4 N), warp tile 64x32.
// 3-split per k16: Ah*Bh + Al*Bh + Ah*Bl (fp32 accum).
// MODE 0: C fp32.  MODE 1: + bias[n].  MODE 2: exp epilogue -> Hout/Lout bf16
// planes + atomicAdd rowsums.  MODE 3: (bias, scale cols<512 by 0.125) ->
// Hout/Lout bf16 planes; blockIdx.x==0 blocks also zero g_S.
// z decomposed as (z1, z2) = (z/zdiv, z%zdiv); offsets z1*s?1 + z2*s?2.
// Smem stage: 4 planes x (128 rows x 80B pitch) = 40960 B; 2 stages.
// ---------------------------------------------------------------------------
#define PITCH 80
#define PLANE_BYTES (128 * PITCH)       // 10240
#define STAGE_BYTES (4 * PLANE_BYTES)   // 40960

template<int MODE>
__global__ void __launch_bounds__(256)
hmma_gemm(const __nv_bfloat16* __restrict__ Ah, const __nv_bfloat16* __restrict__ Al,
          const __nv_bfloat16* __restrict__ Bh, const __nv_bfloat16* __restrict__ Bl,
          float* __restrict__ C, const float* __restrict__ bias,
          __nv_bfloat16* __restrict__ Hout, __nv_bfloat16* __restrict__ Lout,
          float* __restrict__ rowsum,
          int K, int lda, int ldb, int ldc, int zdiv,
          long long sA1, long long sA2, long long sB1, long long sB2,
          long long sC1, long long sC2, long long sR1, long long sR2)
{
    extern __shared__ __align__(16) char smem[];
    const uint32_t sb = smem_u32(smem);

    const int tid = threadIdx.x;
    const int lane = tid & 31, wid = tid >> 5;
    const int wm = wid & 1, wn = wid >> 1;
    const int m0 = blockIdx.y * 128, n0 = blockIdx.x * 128;
    const int z1 = blockIdx.z / zdiv, z2 = blockIdx.z % zdiv;
    const long long zA = z1 * sA1 + z2 * sA2;
    const long long zB = z1 * sB1 + z2 * sB2;
    const long long zC = z1 * sC1 + z2 * sC2;
    Ah += zA; Al += zA; Bh += zB; Bl += zB;

    if (MODE == 3 && blockIdx.x == 0) {
        // zero rowsum accumulators for the downstream E GEMM (8192 floats)
        g_S[blockIdx.y * 256 + tid] = 0.0f;
    }

    // loader: 64 threads per plane (0 Ahi, 1 Alo, 2 Bhi, 3 Blo)
    const int tsel = tid >> 6;
    const __nv_bfloat16* gbase =
        (tsel == 0) ? Ah : (tsel == 1) ? Al : (tsel == 2) ? Bh : Bl;
    const int row0 = (tsel < 2) ? m0 : n0;
    const int ld   = (tsel < 2) ? lda : ldb;
    const int r64  = tid & 63;
    const uint32_t plane_off = (uint32_t)tsel * PLANE_BYTES;

    const int nch = K >> 5;

#define LOAD_CHUNK(buf, k0) do { \
    uint32_t st_ = sb + (buf) * STAGE_BYTES + plane_off; \
    _Pragma("unroll") \
    for (int it_ = 0; it_ < 8; it_++) { \
        int idx_ = r64 + it_ * 64; \
        int row_ = idx_ >> 2, seg_ = idx_ & 3; \
        const __nv_bfloat16* g_ = gbase + (long long)(row0 + row_) * ld + (k0) + seg_ * 8; \
        cp16(st_ + row_ * PITCH + seg_ * 16, g_); \
    } \
    CP_COMMIT(); \
} while (0)

    LOAD_CHUNK(0, 0);

    float c[4][4][4];
#pragma unroll
    for (int a = 0; a < 4; a++)
#pragma unroll
        for (int b = 0; b < 4; b++)
#pragma unroll
            for (int q = 0; q < 4; q++) c[a][b][q] = 0.0f;

    for (int i = 0; i < nch; i++) {
        if (i + 1 < nch) {
            LOAD_CHUNK((i + 1) & 1, (i + 1) * 32);
            CP_WAIT(1);
        } else {
            CP_WAIT(0);
        }
        __syncthreads();

        const uint32_t stg = sb + (i & 1) * STAGE_BYTES;
        const uint32_t a_row_off = (uint32_t)(wm * 64 + (lane & 15)) * PITCH + (lane >> 4) * 16;
        const uint32_t b_row_off = (uint32_t)(wn * 32 + (lane & 7)) * PITCH + ((lane >> 3) & 1) * 16;

#pragma unroll
        for (int k16 = 0; k16 < 2; k16++) {
            uint32_t ah[4][4], al[4][4], bh[4][2], bl[4][2];
            const uint32_t ko = k16 * 32;
#pragma unroll
            for (int tm = 0; tm < 4; tm++) {
                ldsm_x4(ah[tm], stg + 0 * PLANE_BYTES + tm * 16 * PITCH + a_row_off + ko);
                ldsm_x4(al[tm], stg + 1 * PLANE_BYTES + tm * 16 * PITCH + a_row_off + ko);
            }
#pragma unroll
            for (int tn = 0; tn < 4; tn++) {
                ldsm_x2(bh[tn], stg + 2 * PLANE_BYTES + tn * 8 * PITCH + b_row_off + ko);
                ldsm_x2(bl[tn], stg + 3 * PLANE_BYTES + tn * 8 * PITCH + b_row_off + ko);
            }
#pragma unroll
            for (int tm = 0; tm < 4; tm++)
#pragma unroll
                for (int tn = 0; tn < 4; tn++) {
                    mma16816(c[tm][tn], ah[tm], bh[tn]);
                    mma16816(c[tm][tn], al[tm], bh[tn]);
                    mma16816(c[tm][tn], ah[tm], bl[tn]);
                }
        }
        __syncthreads();
    }
#undef LOAD_CHUNK

    // ------------------ epilogue ------------------
    // c[tm][tn][{0,1}] -> row r0 = m0+wm*64+tm*16+(lane>>2),   col+{0,1}
    // c[tm][tn][{2,3}] -> row r0+8
    // col = n0 + wn*32 + tn*8 + (lane&3)*2
    if (MODE == 2) {
#pragma unroll
        for (int tm = 0; tm < 4; tm++) {
            const int r0 = m0 + wm * 64 + tm * 16 + (lane >> 2);
            float s0 = 0.0f, s1 = 0.0f;
#pragma unroll
            for (int tn = 0; tn < 4; tn++) {
                const int col = n0 + wn * 32 + tn * 8 + (lane & 3) * 2;
                float e0 = fast_exp(c[tm][tn][0]);
                float e1 = fast_exp(c[tm][tn][1]);
                float e2 = fast_exp(c[tm][tn][2]);
                float e3 = fast_exp(c[tm][tn][3]);
                s0 += e0 + e1; s1 += e2 + e3;
                __nv_bfloat16 h0 = __float2bfloat16(e0), h1 = __float2bfloat16(e1);
                __nv_bfloat16 h2 = __float2bfloat16(e2), h3 = __float2bfloat16(e3);
                __nv_bfloat16 l0 = __float2bfloat16(e0 - __bfloat162float(h0));
                __nv_bfloat16 l1 = __float2bfloat16(e1 - __bfloat162float(h1));
                __nv_bfloat16 l2 = __float2bfloat16(e2 - __bfloat162float(h2));
                __nv_bfloat16 l3 = __float2bfloat16(e3 - __bfloat162float(h3));
                long long o0 = zC + (long long)r0 * ldc + col;
                long long o1 = o0 + 8LL * ldc;
                *reinterpret_cast<uint32_t*>(Hout + o0) = pack_bf2(h0, h1);
                *reinterpret_cast<uint32_t*>(Lout + o0) = pack_bf2(l0, l1);
                *reinterpret_cast<uint32_t*>(Hout + o1) = pack_bf2(h2, h3);
                *reinterpret_cast<uint32_t*>(Lout + o1) = pack_bf2(l2, l3);
            }
            s0 += __shfl_xor_sync(0xFFFFFFFFu, s0, 1);
            s0 += __shfl_xor_sync(0xFFFFFFFFu, s0, 2);
            s1 += __shfl_xor_sync(0xFFFFFFFFu, s1, 1);
            s1 += __shfl_xor_sync(0xFFFFFFFFu, s1, 2);
            if ((lane & 3) == 0) {
                long long ro = z1 * sR1 + z2 * sR2;
                atomicAdd(rowsum + ro + r0, s0);
                atomicAdd(rowsum + ro + r0 + 8, s1);
            }
        }
    } else if (MODE == 3) {
#pragma unroll
        for (int tm = 0; tm < 4; tm++) {
            const int r0 = m0 + wm * 64 + tm * 16 + (lane >> 2);
#pragma unroll
            for (int tn = 0; tn < 4; tn++) {
                const int col = n0 + wn * 32 + tn * 8 + (lane & 3) * 2;
                const float sc = (col < 512) ? 0.125f : 1.0f;
                float v0 = (c[tm][tn][0] + bias[col])     * sc;
                float v1 = (c[tm][tn][1] + bias[col + 1]) * sc;
                float v2 = (c[tm][tn][2] + bias[col])     * sc;
                float v3 = (c[tm][tn][3] + bias[col + 1]) * sc;
                __nv_bfloat16 h0 = __float2bfloat16(v0), h1 = __float2bfloat16(v1);
                __nv_bfloat16 h2 = __float2bfloat16(v2), h3 = __float2bfloat16(v3);
                __nv_bfloat16 l0 = __float2bfloat16(v0 - __bfloat162float(h0));
                __nv_bfloat16 l1 = __float2bfloat16(v1 - __bfloat162float(h1));
                __nv_bfloat16 l2 = __float2bfloat16(v2 - __bfloat162float(h2));
                __nv_bfloat16 l3 = __float2bfloat16(v3 - __bfloat162float(h3));
                long long o0 = zC + (long long)r0 * ldc + col;
                long long o1 = o0 + 8LL * ldc;
                *reinterpret_cast<uint32_t*>(Hout + o0) = pack_bf2(h0, h1);
                *reinterpret_cast<uint32_t*>(Lout + o0) = pack_bf2(l0, l1);
                *reinterpret_cast<uint32_t*>(Hout + o1) = pack_bf2(h2, h3);
                *reinterpret_cast<uint32_t*>(Lout + o1) = pack_bf2(l2, l3);
            }
        }
    } else {
#pragma unroll
        for (int tm = 0; tm < 4; tm++) {
            const int r0 = m0 + wm * 64 + tm * 16 + (lane >> 2);
#pragma unroll
            for (int tn = 0; tn < 4; tn++) {
                const int col = n0 + wn * 32 + tn * 8 + (lane & 3) * 2;
                float2 v0 = make_float2(c[tm][tn][0], c[tm][tn][1]);
                float2 v1 = make_float2(c[tm][tn][2], c[tm][tn][3]);
                if (MODE == 1) {
                    v0.x += bias[col]; v0.y += bias[col + 1];
                    v1.x += bias[col]; v1.y += bias[col + 1];
                }
                long long o0 = zC + (long long)r0 * ldc + col;
                *reinterpret_cast<float2*>(C + o0) = v0;
                *reinterpret_cast<float2*>(C + o0 + 8LL * ldc) = v1;
            }
        }
    }
}

// ---------------------------------------------------------------------------
// prep: bv@Wo partials (grid (2,64)) + lambda (block (0,0), warp 0)
// ---------------------------------------------------------------------------
__global__ void prep_kernel(const float* __restrict__ bv, const float* __restrict__ Wo,
                            const float* __restrict__ lq1, const float* __restrict__ lk1,
                            const float* __restrict__ lq2, const float* __restrict__ lk2)
{
    if (blockIdx.x == 0 && blockIdx.y == 0 && threadIdx.x < 32) {
        int t = threadIdx.x;
        float a = lq1[t] * lk1[t] + lq1[t + 32] * lk1[t + 32];
        float b = lq2[t] * lk2[t] + lq2[t + 32] * lk2[t + 32];
#pragma unroll
        for (int o = 16; o > 0; o >>= 1) {
            a += __shfl_down_sync(0xFFFFFFFFu, a, o);
            b += __shfl_down_sync(0xFFFFFFFFu, b, o);
        }
        if (t == 0)
            g_lam = expf(a) - expf(b) + (0.8f - 0.6f);
    }
    int j  = blockIdx.x * 256 + threadIdx.x;   // 0..511
    int k0 = blockIdx.y * 128;
    float s = 0.0f;
#pragma unroll 4
    for (int k = k0; k < k0 + 128; k++)
        s = fmaf(bv[k], Wo[(long long)k * 512 + j], s);
    g_bfp[blockIdx.y * 512 + j] = s;
}

// ---------------------------------------------------------------------------
// x -> {xh,xl} (row-major) AND {xTh,xTl} (transposed per batch), one pass
// ---------------------------------------------------------------------------
__global__ void conv_x_kernel(const float* __restrict__ x)
{
    __shared__ float tile[32][33];
    const int z = blockIdx.z;                    // batch
    const int c0 = blockIdx.x * 32, r0 = blockIdx.y * 32;
    const int tx = threadIdx.x, ty = threadIdx.y;
    const float* src = x + (long long)z * 2048 * 512;
#pragma unroll
    for (int j = 0; j < 32; j += 8) {
        float v = src[(long long)(r0 + ty + j) * 512 + c0 + tx];
        tile[ty + j][tx] = v;
        long long o = ((long long)z * 2048 + r0 + ty + j) * 512 + c0 + tx;
        __nv_bfloat16 h = __float2bfloat16(v);
        g_xh[o] = h;
        g_xl[o] = __float2bfloat16(v - __bfloat162float(h));
    }
    __syncthreads();
#pragma unroll
    for (int j = 0; j < 32; j += 8) {
        float v = tile[tx][ty + j];
        long long o = (long long)z * 512 * 2048 + (long long)(c0 + ty + j) * 2048 + r0 + tx;
        __nv_bfloat16 h = __float2bfloat16(v);
        g_xTh[o] = h;
        g_xTl[o] = __float2bfloat16(v - __bfloat162float(h));
    }
}

// transpose fp32 [R,C] -> bf16 hi/lo [C,R]
__global__ void conv_trans(const float* __restrict__ src,
                           __nv_bfloat16* __restrict__ dh, __nv_bfloat16* __restrict__ dl,
                           int R, int C)
{
    __shared__ float tile[32][33];
    int c0 = blockIdx.x * 32, r0 = blockIdx.y * 32;
    int tx = threadIdx.x, ty = threadIdx.y;
#pragma unroll
    for (int j = 0; j < 32; j += 8)
        tile[ty + j][tx] = src[(long long)(r0 + ty + j) * C + c0 + tx];
    __syncthreads();
#pragma unroll
    for (int j = 0; j < 32; j += 8) {
        float v = tile[tx][ty + j];
        long long o = (long long)(c0 + ty + j) * R + r0 + tx;
        __nv_bfloat16 h = __float2bfloat16(v);
        dh[o] = h;
        dl[o] = __float2bfloat16(v - __bfloat162float(h));
    }
}

// fp32 -> bf16 hi/lo
__global__ void conv_plain(const float* __restrict__ src,
                           __nv_bfloat16* __restrict__ hi, __nv_bfloat16* __restrict__ lo,
                           long long n)
{
    long long i = (long long)blockIdx.x * 256 + threadIdx.x;
    if (i >= n) return;
    float v = src[i];
    __nv_bfloat16 h = __float2bfloat16(v);
    hi[i] = h;
    lo[i] = __float2bfloat16(v - __bfloat162float(h));
}

// t = (1/S1) o u1 - (lam/S2) o u2  -> bf16 hi/lo
__global__ void combine_kernel()
{
    long long i = (long long)blockIdx.x * 256 + threadIdx.x;   // over 4096*512
    int row = (int)(i >> 9);
    float c1 = 1.0f / g_S[row];
    float c2 = g_lam / g_S[4096 + row];
    float v = c1 * g_u[i] - c2 * g_u[i + 2097152];
    __nv_bfloat16 h = __float2bfloat16(v);
    g_th[i] = h;
    g_tl[i] = __float2bfloat16(v - __bfloat162float(h));
}

// reduce 8 split-K slabs of W2^T -> bf16 hi/lo; blocks 0-1 also build bfin
__global__ void w2_reduce_conv(const float* __restrict__ bo)
{
    int i = blockIdx.x * 256 + threadIdx.x;   // 0..262143
    float s = 0.0f;
#pragma unroll
    for (int z = 0; z < 8; z++) s += g_W2p[(long long)z * 262144 + i];
    __nv_bfloat16 h = __float2bfloat16(s);
    g_w2Th[i] = h;
    g_w2Tl[i] = __float2bfloat16(s - __bfloat162float(h));

    if (blockIdx.x < 2) {
        int j = i;  // 0..511
        float b = 0.0f;
#pragma unroll
        for (int z = 0; z < 64; z++) b += g_bfp[z * 512 + j];
        g_bfin[j] = fmaf(1.0f - g_lam, b, bo[j]);
    }
}

// ---------------------------------------------------------------------------
// Host orchestration
// ---------------------------------------------------------------------------
extern "C" void kernel_launch(void* const* d_in, const int* in_sizes, int n_in,
                              void* d_out, int out_size)
{
    const float* x    = (const float*)d_in[0];
    const float* Wqkv = (const float*)d_in[1];
    const float* bqkv = (const float*)d_in[2];
    const float* Wv   = (const float*)d_in[3];
    const float* bv   = (const float*)d_in[4];
    const float* Wo   = (const float*)d_in[5];
    const float* bo   = (const float*)d_in[6];
    const float* lq1  = (const float*)d_in[7];
    const float* lk1  = (const float*)d_in[8];
    const float* lq2  = (const float*)d_in[9];
    const float* lk2  = (const float*)d_in[10];
    float* out = (float*)d_out;

    const int SMEM = 2 * STAGE_BYTES;   // 81920
    cudaFuncSetAttribute(hmma_gemm<0>, cudaFuncAttributeMaxDynamicSharedMemorySize, SMEM);
    cudaFuncSetAttribute(hmma_gemm<1>, cudaFuncAttributeMaxDynamicSharedMemorySize, SMEM);
    cudaFuncSetAttribute(hmma_gemm<2>, cudaFuncAttributeMaxDynamicSharedMemorySize, SMEM);
    cudaFuncSetAttribute(hmma_gemm<3>, cudaFuncAttributeMaxDynamicSharedMemorySize, SMEM);

#define SYM(v, s) cudaGetSymbolAddress((void**)&v, s)
    float *W2p, *S, *u, *bfin;
    __nv_bfloat16 *qkvh, *qkvl, *xh, *xl, *xTh, *xTl, *wqTh, *wqTl;
    __nv_bfloat16 *woTh, *woTl, *wvh, *wvl, *Ehp, *Elp, *th, *tl, *w2Th, *w2Tl;
    SYM(W2p, g_W2p); SYM(S, g_S); SYM(u, g_u); SYM(bfin, g_bfin);
    SYM(qkvh, g_qkvh); SYM(qkvl, g_qkvl); SYM(xh, g_xh); SYM(xl, g_xl);
    SYM(xTh, g_xTh); SYM(xTl, g_xTl); SYM(wqTh, g_wqTh); SYM(wqTl, g_wqTl);
    SYM(woTh, g_woTh); SYM(woTl, g_woTl); SYM(wvh, g_wvh); SYM(wvl, g_wvl);
    SYM(Ehp, g_Eh); SYM(Elp, g_El); SYM(th, g_th); SYM(tl, g_tl);
    SYM(w2Th, g_w2Th); SYM(w2Tl, g_w2Tl);
#undef SYM

    const long long PS = 2048LL * 2048;

    // (0) x -> hi/lo plain + transposed
    conv_x_kernel<<<dim3(16, 64, 2), dim3(32, 8)>>>(x);
    // (1) Wqkv^T -> bf16 hi/lo
    conv_trans<<<dim3(32, 16, 1), dim3(32, 8)>>>(Wqkv, wqTh, wqTl, 512, 1024);
    // (2) qkv GEMM: bf16 hi/lo epilogue with bias + Q-scale; zeroes g_S
    hmma_gemm<3><<<dim3(8, 32, 1), 256, SMEM>>>(xh, xl, wqTh, wqTl,
        nullptr, bqkv, qkvh, qkvl, nullptr, 512, 512, 512, 1024, 1,
        0, 0, 0, 0, 0, 0, 0, 0);
    // (3) E = exp(Q K^T) for both maps+batches; z = map*2 + batch  [PROFILED]
    hmma_gemm<2><<<dim3(16, 16, 4), 256, SMEM>>>(qkvh, qkvl, qkvh + 512, qkvl + 512,
        nullptr, nullptr, Ehp, Elp, S, 256, 1024, 1024, 2048, 2,
        256, 2048LL * 1024, 256, 2048LL * 1024, 2 * PS, PS, 4096, 2048);
    // (4) prep: lambda + bv@Wo partials
    prep_kernel<<<dim3(2, 64), 256>>>(bv, Wo, lq1, lk1, lq2, lk2);
    // (5) u = E @ x for both maps+batches; z = map*2 + batch
    hmma_gemm<0><<<dim3(4, 16, 4), 256, SMEM>>>(Ehp, Elp, xTh, xTl, u,
        nullptr, nullptr, nullptr, nullptr, 2048, 2048, 2048, 512, 2,
        2 * PS, PS, 0, 512LL * 2048, 2LL * 2048 * 512, 2048LL * 512, 0, 0);
    // (6) t = c1 o u1 - c2 o u2 -> bf16 hi/lo
    combine_kernel<<<(4096 * 512) / 256, 256>>>();
    // (7,8) Wo^T, Wv -> bf16 hi/lo
    conv_trans<<<dim3(16, 256, 1), dim3(32, 8)>>>(Wo, woTh, woTl, 8192, 512);
    conv_plain<<<(512 * 8192) / 256, 256>>>(Wv, wvh, wvl, 512LL * 8192);
    // (9) W2^T = Wo^T @ Wv^T, split-K x8
    hmma_gemm<0><<<dim3(4, 4, 8), 256, SMEM>>>(woTh, woTl, wvh, wvl, W2p,
        nullptr, nullptr, nullptr, nullptr, 1024, 8192, 8192, 512, 1,
        1024, 0, 1024, 0, 262144, 0, 0, 0);
    // (10) reduce W2 slabs -> bf16 hi/lo; also bfin = (1-lam)*(bv@Wo)+bo
    w2_reduce_conv<<<1024, 256>>>(bo);
    // (11) out = t @ W2 + bfin
    hmma_gemm<1><<<dim3(4, 32, 1), 256, SMEM>>>(th, tl, w2Th, w2Tl, out, bfin,
        nullptr, nullptr, nullptr, 512, 512, 512, 512, 1,
        0, 0, 0, 0, 0, 0, 0, 0);
}

// round 8
// speedup vs baseline: 1.8340x; 1.1178x over previous
#include <cuda_runtime.h>
#include <cuda_bf16.h>
#include <stdint.h>

// ============================================================================
// DifferentialAttention — round 8: 2 CTAs/SM via register diet
//
// Round-7 ncu (E-GEMM): tensor=38%, occ=12.4% (1 CTA/SM, regs=142 -> 2 CTAs
// over the 64K reg file), DRAM=3%. Latency-bound. Fix: restructure inner loop
// to shrink live fragments (load B frags per k16, A frags per tm) and force
// __launch_bounds__(256, 2). Same tiling, same MMA count, same numerics.
//
//  out = diff @ x @ (Wv@Wo) + (1-lam)*(bv@Wo) + bo
//  diff = softmax(Q1K1^T/8) - lam*softmax(Q2K2^T/8); exp fused into logits
//  GEMM epilogue (no max-sub), normalization folded:
//  t = (1/S1) o (E1@x) - (lam/S2) o (E2@x)
// ============================================================================

#define SEQ 2048

// ---------------------------------------------------------------------------
// Scratch (device globals)
// ---------------------------------------------------------------------------
__device__ __align__(16) __nv_bfloat16 g_qkvh[4096 * 1024];
__device__ __align__(16) __nv_bfloat16 g_qkvl[4096 * 1024];
__device__ __align__(16) __nv_bfloat16 g_xh[4096 * 512];
__device__ __align__(16) __nv_bfloat16 g_xl[4096 * 512];
__device__ __align__(16) __nv_bfloat16 g_xTh[2 * 512 * 2048];
__device__ __align__(16) __nv_bfloat16 g_xTl[2 * 512 * 2048];
__device__ __align__(16) __nv_bfloat16 g_wqTh[1024 * 512];
__device__ __align__(16) __nv_bfloat16 g_wqTl[1024 * 512];
__device__ __align__(16) __nv_bfloat16 g_woTh[512 * 8192];
__device__ __align__(16) __nv_bfloat16 g_woTl[512 * 8192];
__device__ __align__(16) __nv_bfloat16 g_wvh[512 * 8192];
__device__ __align__(16) __nv_bfloat16 g_wvl[512 * 8192];
__device__ __align__(16) __nv_bfloat16 g_Eh[2LL * 2 * 2048 * 2048]; // [map][b][S][S]
__device__ __align__(16) __nv_bfloat16 g_El[2LL * 2 * 2048 * 2048];
__device__ float g_S[2 * 4096];                            // rowsums [map][b*S+r]
__device__ __align__(16) float g_u[2LL * 2 * 2048 * 512];  // [map][b][S][512]
__device__ __align__(16) __nv_bfloat16 g_th[4096 * 512];
__device__ __align__(16) __nv_bfloat16 g_tl[4096 * 512];
__device__ __align__(16) float g_W2p[8 * 512 * 512];
__device__ __align__(16) __nv_bfloat16 g_w2Th[512 * 512];
__device__ __align__(16) __nv_bfloat16 g_w2Tl[512 * 512];
__device__ float g_bfp[64 * 512];
__device__ float g_bfin[512];
__device__ float g_lam;

// ---------------------------------------------------------------------------
// PTX helpers (sm_80-era, valid on base sm_100)
// ---------------------------------------------------------------------------
__device__ __forceinline__ uint32_t smem_u32(const void* p) {
    uint32_t a;
    asm("{ .reg .u64 t; cvta.to.shared.u64 t, %1; cvt.u32.u64 %0, t; }"
        : "=r"(a) : "l"(p));
    return a;
}
__device__ __forceinline__ void cp16(uint32_t s, const void* g) {
    asm volatile("cp.async.cg.shared.global [%0], [%1], 16;" :: "r"(s), "l"(g));
}
#define CP_COMMIT() asm volatile("cp.async.commit_group;")
#define CP_WAIT(n)  asm volatile("cp.async.wait_group %0;" :: "n"(n))

__device__ __forceinline__ void ldsm_x4(uint32_t* r, uint32_t a) {
    asm volatile("ldmatrix.sync.aligned.m8n8.x4.shared.b16 {%0,%1,%2,%3}, [%4];"
                 : "=r"(r[0]), "=r"(r[1]), "=r"(r[2]), "=r"(r[3]) : "r"(a));
}
__device__ __forceinline__ void ldsm_x2(uint32_t* r, uint32_t a) {
    asm volatile("ldmatrix.sync.aligned.m8n8.x2.shared.b16 {%0,%1}, [%2];"
                 : "=r"(r[0]), "=r"(r[1]) : "r"(a));
}
__device__ __forceinline__ void mma16816(float* c, const uint32_t* a, const uint32_t* b) {
    asm volatile("mma.sync.aligned.m16n8k16.row.col.f32.bf16.bf16.f32 "
                 "{%0,%1,%2,%3}, {%4,%5,%6,%7}, {%8,%9}, {%0,%1,%2,%3};"
                 : "+f"(c[0]), "+f"(c[1]), "+f"(c[2]), "+f"(c[3])
                 : "r"(a[0]), "r"(a[1]), "r"(a[2]), "r"(a[3]), "r"(b[0]), "r"(b[1]));
}

// ---------------------------------------------------------------------------
// fast exp (FMA pipe, rel err ~2.4e-6)
// ---------------------------------------------------------------------------
__device__ __forceinline__ float fast_exp(float x) {
    x = fmaxf(x, -87.0f);
    float z  = x * 1.4426950408889634f;
    float nf = z + 12582912.0f;
    int   ei = __float_as_int(nf) - 0x4B400000;
    float f  = z - (nf - 12582912.0f);
    float p  =        1.3333558146e-3f;
    p = fmaf(p, f,    9.6181291e-3f);
    p = fmaf(p, f,    5.5504108664e-2f);
    p = fmaf(p, f,    2.4022650696e-1f);
    p = fmaf(p, f,    6.9314718056e-1f);
    p = fmaf(p, f,    1.0f);
    return __int_as_float(__float_as_int(p) + (ei << 23));
}
__device__ __forceinline__ uint32_t pack_bf2(__nv_bfloat16 a, __nv_bfloat16 b) {
    return (uint32_t)__bfloat16_as_ushort(a) | ((uint32_t)__bfloat16_as_ushort(b) << 16);
}

// ---------------------------------------------------------------------------
// HMMA GEMM: C = A @ B^T, A [M,K] hi/lo bf16 row-major, B [N,K] hi/lo.
// Block 128x128, K-chunk 32, 8 warps (2 M x 4 N), warp tile 64x32.
// 3-split per k16: Ah*Bh + Al*Bh + Ah*Bl (fp32 accum).
// MODE 0: C fp32.  MODE 1: + bias[n].  MODE 2: exp epilogue -> Hout/Lout bf16
// planes + atomicAdd rowsums.  MODE 3: (bias, scale cols<512 by 0.125) ->
// Hout/Lout bf16 planes; blockIdx.x==0 blocks also zero g_S.
// z decomposed as (z1, z2) = (z/zdiv, z%zdiv); offsets z1*s?1 + z2*s?2.
// Smem stage: 4 planes x (128 rows x 80B pitch) = 40960 B; 2 stages.
// 2 CTAs/SM (register-dieted mainloop + launch_bounds min-blocks 2).
// ---------------------------------------------------------------------------
#define PITCH 80
#define PLANE_BYTES (128 * PITCH)       // 10240
#define STAGE_BYTES (4 * PLANE_BYTES)   // 40960

template<int MODE>
__global__ void __launch_bounds__(256, 2)
hmma_gemm(const __nv_bfloat16* __restrict__ Ah, const __nv_bfloat16* __restrict__ Al,
          const __nv_bfloat16* __restrict__ Bh, const __nv_bfloat16* __restrict__ Bl,
          float* __restrict__ C, const float* __restrict__ bias,
          __nv_bfloat16* __restrict__ Hout, __nv_bfloat16* __restrict__ Lout,
          float* __restrict__ rowsum,
          int K, int lda, int ldb, int ldc, int zdiv,
          long long sA1, long long sA2, long long sB1, long long sB2,
          long long sC1, long long sC2, long long sR1, long long sR2)
{
    extern __shared__ __align__(16) char smem[];
    const uint32_t sb = smem_u32(smem);

    const int tid = threadIdx.x;
    const int lane = tid & 31, wid = tid >> 5;
    const int wm = wid & 1, wn = wid >> 1;
    const int m0 = blockIdx.y * 128, n0 = blockIdx.x * 128;
    const int z1 = blockIdx.z / zdiv, z2 = blockIdx.z % zdiv;
    const long long zA = z1 * sA1 + z2 * sA2;
    const long long zB = z1 * sB1 + z2 * sB2;
    const long long zC = z1 * sC1 + z2 * sC2;
    Ah += zA; Al += zA; Bh += zB; Bl += zB;

    if (MODE == 3 && blockIdx.x == 0) {
        // zero rowsum accumulators for the downstream E GEMM (8192 floats)
        g_S[blockIdx.y * 256 + tid] = 0.0f;
    }

    // loader: 64 threads per plane (0 Ahi, 1 Alo, 2 Bhi, 3 Blo)
    const int tsel = tid >> 6;
    const __nv_bfloat16* gbase =
        (tsel == 0) ? Ah : (tsel == 1) ? Al : (tsel == 2) ? Bh : Bl;
    const int row0 = (tsel < 2) ? m0 : n0;
    const int ld   = (tsel < 2) ? lda : ldb;
    const int r64  = tid & 63;
    const uint32_t plane_off = (uint32_t)tsel * PLANE_BYTES;

    const int nch = K >> 5;

#define LOAD_CHUNK(buf, k0) do { \
    uint32_t st_ = sb + (buf) * STAGE_BYTES + plane_off; \
    _Pragma("unroll") \
    for (int it_ = 0; it_ < 8; it_++) { \
        int idx_ = r64 + it_ * 64; \
        int row_ = idx_ >> 2, seg_ = idx_ & 3; \
        const __nv_bfloat16* g_ = gbase + (long long)(row0 + row_) * ld + (k0) + seg_ * 8; \
        cp16(st_ + row_ * PITCH + seg_ * 16, g_); \
    } \
    CP_COMMIT(); \
} while (0)

    LOAD_CHUNK(0, 0);

    float c[4][4][4];
#pragma unroll
    for (int a = 0; a < 4; a++)
#pragma unroll
        for (int b = 0; b < 4; b++)
#pragma unroll
            for (int q = 0; q < 4; q++) c[a][b][q] = 0.0f;

    for (int i = 0; i < nch; i++) {
        if (i + 1 < nch) {
            LOAD_CHUNK((i + 1) & 1, (i + 1) * 32);
            CP_WAIT(1);
        } else {
            CP_WAIT(0);
        }
        __syncthreads();

        const uint32_t stg = sb + (i & 1) * STAGE_BYTES;
        const uint32_t a_row_off = (uint32_t)(wm * 64 + (lane & 15)) * PITCH + (lane >> 4) * 16;
        const uint32_t b_row_off = (uint32_t)(wn * 32 + (lane & 7)) * PITCH + ((lane >> 3) & 1) * 16;

#pragma unroll
        for (int k16 = 0; k16 < 2; k16++) {
            const uint32_t ko = k16 * 32;
            // B fragments for this k16 (live: 16 regs)
            uint32_t bh[4][2], bl[4][2];
#pragma unroll
            for (int tn = 0; tn < 4; tn++) {
                ldsm_x2(bh[tn], stg + 2 * PLANE_BYTES + tn * 8 * PITCH + b_row_off + ko);
                ldsm_x2(bl[tn], stg + 3 * PLANE_BYTES + tn * 8 * PITCH + b_row_off + ko);
            }
            // A fragments per tm (live: 8 regs), MMAs issued immediately
#pragma unroll
            for (int tm = 0; tm < 4; tm++) {
                uint32_t ah[4], al[4];
                ldsm_x4(ah, stg + 0 * PLANE_BYTES + tm * 16 * PITCH + a_row_off + ko);
                ldsm_x4(al, stg + 1 * PLANE_BYTES + tm * 16 * PITCH + a_row_off + ko);
#pragma unroll
                for (int tn = 0; tn < 4; tn++) {
                    mma16816(c[tm][tn], ah, bh[tn]);
                    mma16816(c[tm][tn], al, bh[tn]);
                    mma16816(c[tm][tn], ah, bl[tn]);
                }
            }
        }
        __syncthreads();
    }
#undef LOAD_CHUNK

    // ------------------ epilogue ------------------
    // c[tm][tn][{0,1}] -> row r0 = m0+wm*64+tm*16+(lane>>2),   col+{0,1}
    // c[tm][tn][{2,3}] -> row r0+8
    // col = n0 + wn*32 + tn*8 + (lane&3)*2
    if (MODE == 2) {
#pragma unroll
        for (int tm = 0; tm < 4; tm++) {
            const int r0 = m0 + wm * 64 + tm * 16 + (lane >> 2);
            float s0 = 0.0f, s1 = 0.0f;
#pragma unroll
            for (int tn = 0; tn < 4; tn++) {
                const int col = n0 + wn * 32 + tn * 8 + (lane & 3) * 2;
                float e0 = fast_exp(c[tm][tn][0]);
                float e1 = fast_exp(c[tm][tn][1]);
                float e2 = fast_exp(c[tm][tn][2]);
                float e3 = fast_exp(c[tm][tn][3]);
                s0 += e0 + e1; s1 += e2 + e3;
                __nv_bfloat16 h0 = __float2bfloat16(e0), h1 = __float2bfloat16(e1);
                __nv_bfloat16 h2 = __float2bfloat16(e2), h3 = __float2bfloat16(e3);
                __nv_bfloat16 l0 = __float2bfloat16(e0 - __bfloat162float(h0));
                __nv_bfloat16 l1 = __float2bfloat16(e1 - __bfloat162float(h1));
                __nv_bfloat16 l2 = __float2bfloat16(e2 - __bfloat162float(h2));
                __nv_bfloat16 l3 = __float2bfloat16(e3 - __bfloat162float(h3));
                long long o0 = zC + (long long)r0 * ldc + col;
                long long o1 = o0 + 8LL * ldc;
                *reinterpret_cast<uint32_t*>(Hout + o0) = pack_bf2(h0, h1);
                *reinterpret_cast<uint32_t*>(Lout + o0) = pack_bf2(l0, l1);
                *reinterpret_cast<uint32_t*>(Hout + o1) = pack_bf2(h2, h3);
                *reinterpret_cast<uint32_t*>(Lout + o1) = pack_bf2(l2, l3);
            }
            s0 += __shfl_xor_sync(0xFFFFFFFFu, s0, 1);
            s0 += __shfl_xor_sync(0xFFFFFFFFu, s0, 2);
            s1 += __shfl_xor_sync(0xFFFFFFFFu, s1, 1);
            s1 += __shfl_xor_sync(0xFFFFFFFFu, s1, 2);
            if ((lane & 3) == 0) {
                long long ro = z1 * sR1 + z2 * sR2;
                atomicAdd(rowsum + ro + r0, s0);
                atomicAdd(rowsum + ro + r0 + 8, s1);
            }
        }
    } else if (MODE == 3) {
#pragma unroll
        for (int tm = 0; tm < 4; tm++) {
            const int r0 = m0 + wm * 64 + tm * 16 + (lane >> 2);
#pragma unroll
            for (int tn = 0; tn < 4; tn++) {
                const int col = n0 + wn * 32 + tn * 8 + (lane & 3) * 2;
                const float sc = (col < 512) ? 0.125f : 1.0f;
                float v0 = (c[tm][tn][0] + bias[col])     * sc;
                float v1 = (c[tm][tn][1] + bias[col + 1]) * sc;
                float v2 = (c[tm][tn][2] + bias[col])     * sc;
                float v3 = (c[tm][tn][3] + bias[col + 1]) * sc;
                __nv_bfloat16 h0 = __float2bfloat16(v0), h1 = __float2bfloat16(v1);
                __nv_bfloat16 h2 = __float2bfloat16(v2), h3 = __float2bfloat16(v3);
                __nv_bfloat16 l0 = __float2bfloat16(v0 - __bfloat162float(h0));
                __nv_bfloat16 l1 = __float2bfloat16(v1 - __bfloat162float(h1));
                __nv_bfloat16 l2 = __float2bfloat16(v2 - __bfloat162float(h2));
                __nv_bfloat16 l3 = __float2bfloat16(v3 - __bfloat162float(h3));
                long long o0 = zC + (long long)r0 * ldc + col;
                long long o1 = o0 + 8LL * ldc;
                *reinterpret_cast<uint32_t*>(Hout + o0) = pack_bf2(h0, h1);
                *reinterpret_cast<uint32_t*>(Lout + o0) = pack_bf2(l0, l1);
                *reinterpret_cast<uint32_t*>(Hout + o1) = pack_bf2(h2, h3);
                *reinterpret_cast<uint32_t*>(Lout + o1) = pack_bf2(l2, l3);
            }
        }
    } else {
#pragma unroll
        for (int tm = 0; tm < 4; tm++) {
            const int r0 = m0 + wm * 64 + tm * 16 + (lane >> 2);
#pragma unroll
            for (int tn = 0; tn < 4; tn++) {
                const int col = n0 + wn * 32 + tn * 8 + (lane & 3) * 2;
                float2 v0 = make_float2(c[tm][tn][0], c[tm][tn][1]);
                float2 v1 = make_float2(c[tm][tn][2], c[tm][tn][3]);
                if (MODE == 1) {
                    v0.x += bias[col]; v0.y += bias[col + 1];
                    v1.x += bias[col]; v1.y += bias[col + 1];
                }
                long long o0 = zC + (long long)r0 * ldc + col;
                *reinterpret_cast<float2*>(C + o0) = v0;
                *reinterpret_cast<float2*>(C + o0 + 8LL * ldc) = v1;
            }
        }
    }
}

// ---------------------------------------------------------------------------
// prep: bv@Wo partials (grid (2,64)) + lambda (block (0,0), warp 0)
// ---------------------------------------------------------------------------
__global__ void prep_kernel(const float* __restrict__ bv, const float* __restrict__ Wo,
                            const float* __restrict__ lq1, const float* __restrict__ lk1,
                            const float* __restrict__ lq2, const float* __restrict__ lk2)
{
    if (blockIdx.x == 0 && blockIdx.y == 0 && threadIdx.x < 32) {
        int t = threadIdx.x;
        float a = lq1[t] * lk1[t] + lq1[t + 32] * lk1[t + 32];
        float b = lq2[t] * lk2[t] + lq2[t + 32] * lk2[t + 32];
#pragma unroll
        for (int o = 16; o > 0; o >>= 1) {
            a += __shfl_down_sync(0xFFFFFFFFu, a, o);
            b += __shfl_down_sync(0xFFFFFFFFu, b, o);
        }
        if (t == 0)
            g_lam = expf(a) - expf(b) + (0.8f - 0.6f);
    }
    int j  = blockIdx.x * 256 + threadIdx.x;   // 0..511
    int k0 = blockIdx.y * 128;
    float s = 0.0f;
#pragma unroll 4
    for (int k = k0; k < k0 + 128; k++)
        s = fmaf(bv[k], Wo[(long long)k * 512 + j], s);
    g_bfp[blockIdx.y * 512 + j] = s;
}

// ---------------------------------------------------------------------------
// x -> {xh,xl} (row-major) AND {xTh,xTl} (transposed per batch), one pass
// ---------------------------------------------------------------------------
__global__ void conv_x_kernel(const float* __restrict__ x)
{
    __shared__ float tile[32][33];
    const int z = blockIdx.z;                    // batch
    const int c0 = blockIdx.x * 32, r0 = blockIdx.y * 32;
    const int tx = threadIdx.x, ty = threadIdx.y;
    const float* src = x + (long long)z * 2048 * 512;
#pragma unroll
    for (int j = 0; j < 32; j += 8) {
        float v = src[(long long)(r0 + ty + j) * 512 + c0 + tx];
        tile[ty + j][tx] = v;
        long long o = ((long long)z * 2048 + r0 + ty + j) * 512 + c0 + tx;
        __nv_bfloat16 h = __float2bfloat16(v);
        g_xh[o] = h;
        g_xl[o] = __float2bfloat16(v - __bfloat162float(h));
    }
    __syncthreads();
#pragma unroll
    for (int j = 0; j < 32; j += 8) {
        float v = tile[tx][ty + j];
        long long o = (long long)z * 512 * 2048 + (long long)(c0 + ty + j) * 2048 + r0 + tx;
        __nv_bfloat16 h = __float2bfloat16(v);
        g_xTh[o] = h;
        g_xTl[o] = __float2bfloat16(v - __bfloat162float(h));
    }
}

// transpose fp32 [R,C] -> bf16 hi/lo [C,R]
__global__ void conv_trans(const float* __restrict__ src,
                           __nv_bfloat16* __restrict__ dh, __nv_bfloat16* __restrict__ dl,
                           int R, int C)
{
    __shared__ float tile[32][33];
    int c0 = blockIdx.x * 32, r0 = blockIdx.y * 32;
    int tx = threadIdx.x, ty = threadIdx.y;
#pragma unroll
    for (int j = 0; j < 32; j += 8)
        tile[ty + j][tx] = src[(long long)(r0 + ty + j) * C + c0 + tx];
    __syncthreads();
#pragma unroll
    for (int j = 0; j < 32; j += 8) {
        float v = tile[tx][ty + j];
        long long o = (long long)(c0 + ty + j) * R + r0 + tx;
        __nv_bfloat16 h = __float2bfloat16(v);
        dh[o] = h;
        dl[o] = __float2bfloat16(v - __bfloat162float(h));
    }
}

// fp32 -> bf16 hi/lo
__global__ void conv_plain(const float* __restrict__ src,
                           __nv_bfloat16* __restrict__ hi, __nv_bfloat16* __restrict__ lo,
                           long long n)
{
    long long i = (long long)blockIdx.x * 256 + threadIdx.x;
    if (i >= n) return;
    float v = src[i];
    __nv_bfloat16 h = __float2bfloat16(v);
    hi[i] = h;
    lo[i] = __float2bfloat16(v - __bfloat162float(h));
}

// t = (1/S1) o u1 - (lam/S2) o u2  -> bf16 hi/lo
__global__ void combine_kernel()
{
    long long i = (long long)blockIdx.x * 256 + threadIdx.x;   // over 4096*512
    int row = (int)(i >> 9);
    float c1 = 1.0f / g_S[row];
    float c2 = g_lam / g_S[4096 + row];
    float v = c1 * g_u[i] - c2 * g_u[i + 2097152];
    __nv_bfloat16 h = __float2bfloat16(v);
    g_th[i] = h;
    g_tl[i] = __float2bfloat16(v - __bfloat162float(h));
}

// reduce 8 split-K slabs of W2^T -> bf16 hi/lo; blocks 0-1 also build bfin
__global__ void w2_reduce_conv(const float* __restrict__ bo)
{
    int i = blockIdx.x * 256 + threadIdx.x;   // 0..262143
    float s = 0.0f;
#pragma unroll
    for (int z = 0; z < 8; z++) s += g_W2p[(long long)z * 262144 + i];
    __nv_bfloat16 h = __float2bfloat16(s);
    g_w2Th[i] = h;
    g_w2Tl[i] = __float2bfloat16(s - __bfloat162float(h));

    if (blockIdx.x < 2) {
        int j = i;  // 0..511
        float b = 0.0f;
#pragma unroll
        for (int z = 0; z < 64; z++) b += g_bfp[z * 512 + j];
        g_bfin[j] = fmaf(1.0f - g_lam, b, bo[j]);
    }
}

// ---------------------------------------------------------------------------
// Host orchestration
// ---------------------------------------------------------------------------
extern "C" void kernel_launch(void* const* d_in, const int* in_sizes, int n_in,
                              void* d_out, int out_size)
{
    const float* x    = (const float*)d_in[0];
    const float* Wqkv = (const float*)d_in[1];
    const float* bqkv = (const float*)d_in[2];
    const float* Wv   = (const float*)d_in[3];
    const float* bv   = (const float*)d_in[4];
    const float* Wo   = (const float*)d_in[5];
    const float* bo   = (const float*)d_in[6];
    const float* lq1  = (const float*)d_in[7];
    const float* lk1  = (const float*)d_in[8];
    const float* lq2  = (const float*)d_in[9];
    const float* lk2  = (const float*)d_in[10];
    float* out = (float*)d_out;

    const int SMEM = 2 * STAGE_BYTES;   // 81920
    cudaFuncSetAttribute(hmma_gemm<0>, cudaFuncAttributeMaxDynamicSharedMemorySize, SMEM);
    cudaFuncSetAttribute(hmma_gemm<1>, cudaFuncAttributeMaxDynamicSharedMemorySize, SMEM);
    cudaFuncSetAttribute(hmma_gemm<2>, cudaFuncAttributeMaxDynamicSharedMemorySize, SMEM);
    cudaFuncSetAttribute(hmma_gemm<3>, cudaFuncAttributeMaxDynamicSharedMemorySize, SMEM);

#define SYM(v, s) cudaGetSymbolAddress((void**)&v, s)
    float *W2p, *S, *u, *bfin;
    __nv_bfloat16 *qkvh, *qkvl, *xh, *xl, *xTh, *xTl, *wqTh, *wqTl;
    __nv_bfloat16 *woTh, *woTl, *wvh, *wvl, *Ehp, *Elp, *th, *tl, *w2Th, *w2Tl;
    SYM(W2p, g_W2p); SYM(S, g_S); SYM(u, g_u); SYM(bfin, g_bfin);
    SYM(qkvh, g_qkvh); SYM(qkvl, g_qkvl); SYM(xh, g_xh); SYM(xl, g_xl);
    SYM(xTh, g_xTh); SYM(xTl, g_xTl); SYM(wqTh, g_wqTh); SYM(wqTl, g_wqTl);
    SYM(woTh, g_woTh); SYM(woTl, g_woTl); SYM(wvh, g_wvh); SYM(wvl, g_wvl);
    SYM(Ehp, g_Eh); SYM(Elp, g_El); SYM(th, g_th); SYM(tl, g_tl);
    SYM(w2Th, g_w2Th); SYM(w2Tl, g_w2Tl);
#undef SYM

    const long long PS = 2048LL * 2048;

    // (0) x -> hi/lo plain + transposed
    conv_x_kernel<<<dim3(16, 64, 2), dim3(32, 8)>>>(x);
    // (1) Wqkv^T -> bf16 hi/lo
    conv_trans<<<dim3(32, 16, 1), dim3(32, 8)>>>(Wqkv, wqTh, wqTl, 512, 1024);
    // (2) qkv GEMM: bf16 hi/lo epilogue with bias + Q-scale; zeroes g_S
    hmma_gemm<3><<<dim3(8, 32, 1), 256, SMEM>>>(xh, xl, wqTh, wqTl,
        nullptr, bqkv, qkvh, qkvl, nullptr, 512, 512, 512, 1024, 1,
        0, 0, 0, 0, 0, 0, 0, 0);
    // (3) E = exp(Q K^T) for both maps+batches; z = map*2 + batch  [PROFILED]
    hmma_gemm<2><<<dim3(16, 16, 4), 256, SMEM>>>(qkvh, qkvl, qkvh + 512, qkvl + 512,
        nullptr, nullptr, Ehp, Elp, S, 256, 1024, 1024, 2048, 2,
        256, 2048LL * 1024, 256, 2048LL * 1024, 2 * PS, PS, 4096, 2048);
    // (4) prep: lambda + bv@Wo partials
    prep_kernel<<<dim3(2, 64), 256>>>(bv, Wo, lq1, lk1, lq2, lk2);
    // (5) u = E @ x for both maps+batches; z = map*2 + batch
    hmma_gemm<0><<<dim3(4, 16, 4), 256, SMEM>>>(Ehp, Elp, xTh, xTl, u,
        nullptr, nullptr, nullptr, nullptr, 2048, 2048, 2048, 512, 2,
        2 * PS, PS, 0, 512LL * 2048, 2LL * 2048 * 512, 2048LL * 512, 0, 0);
    // (6) t = c1 o u1 - c2 o u2 -> bf16 hi/lo
    combine_kernel<<<(4096 * 512) / 256, 256>>>();
    // (7,8) Wo^T, Wv -> bf16 hi/lo
    conv_trans<<<dim3(16, 256, 1), dim3(32, 8)>>>(Wo, woTh, woTl, 8192, 512);
    conv_plain<<<(512 * 8192) / 256, 256>>>(Wv, wvh, wvl, 512LL * 8192);
    // (9) W2^T = Wo^T @ Wv^T, split-K x8
    hmma_gemm<0><<<dim3(4, 4, 8), 256, SMEM>>>(woTh, woTl, wvh, wvl, W2p,
        nullptr, nullptr, nullptr, nullptr, 1024, 8192, 8192, 512, 1,
        1024, 0, 1024, 0, 262144, 0, 0, 0);
    // (10) reduce W2 slabs -> bf16 hi/lo; also bfin = (1-lam)*(bv@Wo)+bo
    w2_reduce_conv<<<1024, 256>>>(bo);
    // (11) out = t @ W2 + bfin
    hmma_gemm<1><<<dim3(4, 32, 1), 256, SMEM>>>(th, tl, w2Th, w2Tl, out, bfin,
        nullptr, nullptr, nullptr, 512, 512, 512, 512, 1,
        0, 0, 0, 0, 0, 0, 0, 0);
}